// round 12
// baseline (speedup 1.0000x reference)
#include <cuda_runtime.h>
#include <cuda_fp16.h>
#include <cstdint>

// ============================================================================
// InteractAttention on sm_103 (base target):
//   wpack: weights fp32 [K][256] -> fp16 n-major [256][K] via smem transpose
//   GEMM: 256-thread CTAs, 2 CTAs/SM (independent barriers -> latency overlap),
//         tile M=128 x N=128, KCH=32, padded-80B-row smem, mma.m16n8k16.f16.
//   epilogue: separate fused-row kernel (fusion regressed twice: R9 spills,
//             R10 ABI reg-cap -- reverted for good).
//   g=0: xc@LW1  g=1: xc@AW12  g=2: xc@AW2  g=3: xp@LW2  g=4: xp@AW1  g=5: xp@AW23
// ============================================================================

#define B_ROWS   32768
#define H_DIM    256
#define MT       128
#define KCH      32                     // K chunk (32 halves)
#define STAGES   5
#define NTHREADS 256
#define N_ROW_TILES (B_ROWS / MT)       // 256
#define SCRATCH_PER 8388608ull

__device__ __align__(16) float  g_sf[2ull * SCRATCH_PER];  // 0: cb (g0), 1: pb (g3)
__device__ __align__(16) __half g_sh[4ull * SCRATCH_PER];  // 0:a12 1:a2 2:a1 3:a23
__device__ __align__(16) __half g_wph[2162688];            // n-major fp16 weights

// half offsets of each weight matrix [256][K]
#define WH0 0u          // LW1  K=768
#define WH1 196608u     // AW12
#define WH2 393216u     // AW2
#define WH3 589824u     // LW2  K=2048
#define WH4 1114112u    // AW1
#define WH5 1638400u    // AW23

// smem: padded rows of 32 halves -> 20 words (80B). A: 128 rows, B: 128 rows.
#define ROW_W        20
#define A_STAGE_B    (128 * 80)               // 10240
#define B_STAGE_B    (128 * 80)               // 10240
#define STAGE_BYTES  (A_STAGE_B + B_STAGE_B)  // 20480
#define STAGE_WORDS  (STAGE_BYTES / 4)        // 5120
#define SMEM_BYTES   (STAGES * STAGE_BYTES)   // 102400

__device__ __forceinline__ uint32_t smem_u32(const void* p) {
    uint32_t a;
    asm("{ .reg .u64 t; cvta.to.shared.u64 t, %1; cvt.u32.u64 %0, t; }"
        : "=r"(a) : "l"(p));
    return a;
}
__device__ __forceinline__ void cp16(uint32_t dst, const void* src) {
    asm volatile("cp.async.cg.shared.global [%0], [%1], 16;" :: "r"(dst), "l"(src));
}
__device__ __forceinline__ void mma_f16(float* c, const uint32_t* a, const uint32_t* b) {
    asm volatile(
        "mma.sync.aligned.m16n8k16.row.col.f32.f16.f16.f32 "
        "{%0,%1,%2,%3}, {%4,%5,%6,%7}, {%8,%9}, {%0,%1,%2,%3};"
        : "+f"(c[0]), "+f"(c[1]), "+f"(c[2]), "+f"(c[3])
        : "r"(a[0]), "r"(a[1]), "r"(a[2]), "r"(a[3]), "r"(b[0]), "r"(b[1]));
}
__device__ __forceinline__ uint32_t pack_h2(float lo, float hi) {
    __half2 h = __floats2half2_rn(lo, hi);
    return *reinterpret_cast<uint32_t*>(&h);
}

// ---------------- weight repack: fp32 [K][256] -> fp16 [256][K] -------------
// 64k x 32n tile transpose through smem (stride 35: conflict-free both phases)
__global__ void __launch_bounds__(256)
wpack_kernel(const float* __restrict__ s0, const float* __restrict__ s1,
             const float* __restrict__ s2, const float* __restrict__ s3,
             const float* __restrict__ s4, const float* __restrict__ s5) {
    __shared__ float sm[64 * 35];
    const int kb = blockIdx.x;          // 0..131  (concatenated 64-row k blocks)
    const int nb = blockIdx.y;          // 0..7
    const float* src; int K; unsigned base; int kk;
    if      (kb < 12)  { src = s0; K = 768;  base = WH0; kk = kb; }
    else if (kb < 24)  { src = s1; K = 768;  base = WH1; kk = kb - 12; }
    else if (kb < 36)  { src = s2; K = 768;  base = WH2; kk = kb - 24; }
    else if (kb < 68)  { src = s3; K = 2048; base = WH3; kk = kb - 36; }
    else if (kb < 100) { src = s4; K = 2048; base = WH4; kk = kb - 68; }
    else               { src = s5; K = 2048; base = WH5; kk = kb - 100; }
    const int k0 = kk * 64;
    const int t  = threadIdx.x;
    const int rw = t >> 5, cl = t & 31;

    #pragma unroll
    for (int j = 0; j < 8; j++) {
        const int kr = rw + 8 * j;
        sm[kr * 35 + cl] = src[(size_t)(k0 + kr) * 256 + nb * 32 + cl];
    }
    __syncthreads();

    const int nl = t >> 3;              // 0..31 local n
    const int kg = (t & 7) * 8;         // 0..56 step 8
    uint4 o;
    o.x = pack_h2(sm[(kg + 0) * 35 + nl], sm[(kg + 1) * 35 + nl]);
    o.y = pack_h2(sm[(kg + 2) * 35 + nl], sm[(kg + 3) * 35 + nl]);
    o.z = pack_h2(sm[(kg + 4) * 35 + nl], sm[(kg + 5) * 35 + nl]);
    o.w = pack_h2(sm[(kg + 6) * 35 + nl], sm[(kg + 7) * 35 + nl]);
    const int n = nb * 32 + nl;
    *(uint4*)(g_wph + base + (size_t)n * K + k0 + kg) = o;
}

// ---------------- GEMM: 256 threads, 2 CTAs/SM ----------------
__global__ void __launch_bounds__(NTHREADS, 2)
gemm_f16_kernel(const float* __restrict__ xc, const float* __restrict__ xp) {
    extern __shared__ float smem[];
    const int tid = threadIdx.x;
    const int wid = tid >> 5;           // 0..7
    const int lid = tid & 31;
    const int g8  = lid >> 2;           // 0..7
    const int tg  = lid & 3;            // 0..3
    const int wm  = wid & 3;            // rows wm*32..+31
    const int wn  = wid >> 2;           // 0..1 -> cols wn*64..+63 (within half)

    // pic (K=2048) CTAs first; 6 same-tile CTAs adjacent for L2 A-sharing
    const int bid = blockIdx.x;
    int g, tile, nh;
    if (bid < 6 * N_ROW_TILES) {
        tile = bid / 6; const int r = bid % 6; g = 3 + r / 2; nh = r & 1;
    } else {
        const int b2 = bid - 6 * N_ROW_TILES;
        tile = b2 / 6; const int r = b2 % 6; g = r / 2; nh = r & 1;
    }

    const float* X; const __half* Wl; int K;
    if      (g == 0) { X = xc; Wl = g_wph + WH0; K = 768;  }
    else if (g == 1) { X = xc; Wl = g_wph + WH1; K = 768;  }
    else if (g == 2) { X = xc; Wl = g_wph + WH2; K = 768;  }
    else if (g == 3) { X = xp; Wl = g_wph + WH3; K = 2048; }
    else if (g == 4) { X = xp; Wl = g_wph + WH4; K = 2048; }
    else             { X = xp; Wl = g_wph + WH5; K = 2048; }

    const __half* Wb = Wl + (size_t)(nh * 128) * K;   // this CTA's n-half
    const float*  Xb = X + (size_t)tile * MT * K;
    const uint32_t sb = smem_u32(smem);
    const int NK = K / KCH;             // 24 or 64 chunks

    // per-thread loader coords
    const int am  = tid >> 1;           // A row 0..127
    const int acv = tid & 1;            // half-row (16 floats)

    float c[2][8][4];
    #pragma unroll
    for (int mt = 0; mt < 2; mt++)
        #pragma unroll
        for (int nt = 0; nt < 8; nt++)
            #pragma unroll
            for (int r = 0; r < 4; r++) c[mt][nt][r] = 0.0f;

    // B loader: 128 n-rows x 2 cp16 -> 512 ops / 256 threads = 2 each
    auto load_B = [&](int chunk) {
        const int st = chunk % STAGES;
        const uint32_t stB = sb + st * STAGE_BYTES + A_STAGE_B;
        const int kc = chunk * KCH;
        #pragma unroll
        for (int j = 0; j < 2; j++) {
            const int f = tid + j * NTHREADS;   // 0..511
            const int n = f >> 2;               // 0..127
            const int v = f & 3;                // 16B group
            cp16(stB + n * 80 + v * 16, Wb + (size_t)n * K + kc + v * 8);
        }
        asm volatile("cp.async.commit_group;" ::: "memory");
    };
    // A: 16 floats -> 2 STS.128 into padded row
    auto store_A = [&](int chunk, const float4* r) {
        const int st = chunk % STAGES;
        char* dst = (char*)smem + st * STAGE_BYTES + am * 80 + acv * 32;
        uint4 o0, o1;
        o0.x = pack_h2(r[0].x, r[0].y); o0.y = pack_h2(r[0].z, r[0].w);
        o0.z = pack_h2(r[1].x, r[1].y); o0.w = pack_h2(r[1].z, r[1].w);
        o1.x = pack_h2(r[2].x, r[2].y); o1.y = pack_h2(r[2].z, r[2].w);
        o1.z = pack_h2(r[3].x, r[3].y); o1.w = pack_h2(r[3].z, r[3].w);
        *(uint4*)(dst)      = o0;
        *(uint4*)(dst + 16) = o1;
    };
    auto load_A = [&](int chunk, float4* r) {
        const float* src = Xb + (size_t)am * K + chunk * KCH + acv * 16;
        r[0] = *(const float4*)(src + 0);
        r[1] = *(const float4*)(src + 4);
        r[2] = *(const float4*)(src + 8);
        r[3] = *(const float4*)(src + 12);
    };

    // prologue: stages 0..STAGES-2
    #pragma unroll
    for (int s = 0; s < STAGES - 1; s++) {
        float4 r[4];
        load_A(s, r);
        store_A(s, r);
        load_B(s);
    }

    for (int i = 0; i < NK; i++) {
        asm volatile("cp.async.wait_group %0;" :: "n"(STAGES - 2) : "memory");
        __syncthreads();

        const bool pf = (i + STAGES - 1 < NK);
        float4 rA[4];
        if (pf) { load_A(i + STAGES - 1, rA); load_B(i + STAGES - 1); }

        const int st = i % STAGES;
        const uint32_t* As = (const uint32_t*)smem + st * STAGE_WORDS;
        const uint32_t* Bs = As + (A_STAGE_B / 4);

        #pragma unroll
        for (int s = 0; s < 2; s++) {               // two k16 steps
            const int kl = 8 * s + tg;              // half2 index 0..15
            const int kh = kl + 4;
            uint32_t b[8][2];
            #pragma unroll
            for (int nt = 0; nt < 8; nt++) {
                const int n = wn * 64 + nt * 8 + g8;
                b[nt][0] = Bs[n * ROW_W + kl];
                b[nt][1] = Bs[n * ROW_W + kh];
            }
            uint32_t a[2][4];
            #pragma unroll
            for (int mt = 0; mt < 2; mt++) {
                const int m = wm * 32 + mt * 16 + g8;
                a[mt][0] = As[m * ROW_W + kl];
                a[mt][1] = As[(m + 8) * ROW_W + kl];
                a[mt][2] = As[m * ROW_W + kh];
                a[mt][3] = As[(m + 8) * ROW_W + kh];
            }
            #pragma unroll
            for (int mt = 0; mt < 2; mt++)
                #pragma unroll
                for (int nt = 0; nt < 8; nt++)
                    mma_f16(c[mt][nt], a[mt], b[nt]);
        }

        if (pf) store_A(i + STAGES - 1, rA);
    }

    // ---- writeback (column offset by this CTA's n-half) ----
    const int ncol0 = nh * 128;
    if (g == 0 || g == 3) {
        float* Yf = g_sf + (size_t)(g == 0 ? 0 : 1) * SCRATCH_PER
                         + (size_t)tile * (MT * H_DIM);
        #pragma unroll
        for (int mt = 0; mt < 2; mt++) {
            const int r0 = wm * 32 + mt * 16 + g8;
            #pragma unroll
            for (int nt = 0; nt < 8; nt++) {
                const int col = ncol0 + wn * 64 + nt * 8 + tg * 2;
                *(float2*)(Yf + (size_t)r0 * H_DIM + col) =
                    make_float2(c[mt][nt][0], c[mt][nt][1]);
                *(float2*)(Yf + (size_t)(r0 + 8) * H_DIM + col) =
                    make_float2(c[mt][nt][2], c[mt][nt][3]);
            }
        }
    } else {
        const int idx = (g == 1) ? 0 : (g == 2) ? 1 : (g == 4) ? 2 : 3;
        __half* Yh = g_sh + (size_t)idx * SCRATCH_PER
                          + (size_t)tile * (MT * H_DIM);
        #pragma unroll
        for (int mt = 0; mt < 2; mt++) {
            const int r0 = wm * 32 + mt * 16 + g8;
            #pragma unroll
            for (int nt = 0; nt < 8; nt++) {
                const int col = ncol0 + wn * 64 + nt * 8 + tg * 2;
                *(uint32_t*)(Yh + (size_t)r0 * H_DIM + col) =
                    pack_h2(c[mt][nt][0], c[mt][nt][1]);
                *(uint32_t*)(Yh + (size_t)(r0 + 8) * H_DIM + col) =
                    pack_h2(c[mt][nt][2], c[mt][nt][3]);
            }
        }
    }
}

// ---------------- epilogue: one warp per row ----------------
__device__ __forceinline__ float wsum(float v) {
    #pragma unroll
    for (int o = 16; o; o >>= 1) v += __shfl_xor_sync(0xFFFFFFFFu, v, o);
    return v;
}
__device__ __forceinline__ void load8(float* a, const float* base, int lane) {
    const float4* p = (const float4*)base;
    float4 x = p[lane], y = p[lane + 32];
    a[0]=x.x; a[1]=x.y; a[2]=x.z; a[3]=x.w;
    a[4]=y.x; a[5]=y.y; a[6]=y.z; a[7]=y.w;
}
__device__ __forceinline__ void load8h(float* a, const __half* base, int lane) {
    const uint2* p = (const uint2*)base;
    uint2 x = p[lane], y = p[lane + 32];
    float2 f;
    f = __half22float2(*(__half2*)&x.x); a[0]=f.x; a[1]=f.y;
    f = __half22float2(*(__half2*)&x.y); a[2]=f.x; a[3]=f.y;
    f = __half22float2(*(__half2*)&y.x); a[4]=f.x; a[5]=f.y;
    f = __half22float2(*(__half2*)&y.y); a[6]=f.x; a[7]=f.y;
}
__device__ __forceinline__ void store8(float* base, const float* a, int lane) {
    float4* p = (float4*)base;
    p[lane]      = make_float4(a[0], a[1], a[2], a[3]);
    p[lane + 32] = make_float4(a[4], a[5], a[6], a[7]);
}
__device__ __forceinline__ float sigm(float x) { return 1.0f / (1.0f + __expf(-x)); }
__device__ __forceinline__ float tanh_fast(float x) {
    return 1.0f - 2.0f / (1.0f + __expf(2.0f * x));
}

__global__ void __launch_bounds__(256)
epilogue_kernel(const float* __restrict__ lb1, const float* __restrict__ lb2,
                float* __restrict__ out) {
    const int lane = threadIdx.x & 31;
    const int row  = blockIdx.x * 8 + (threadIdx.x >> 5);
    const size_t off = (size_t)row * H_DIM;

    float cb[8], a12[8], a2[8], pb[8], a1[8], a23[8], b1[8], b2[8];
    load8 (cb,  g_sf + 0 * SCRATCH_PER + off, lane);
    load8 (pb,  g_sf + 1 * SCRATCH_PER + off, lane);
    load8h(a12, g_sh + 0 * SCRATCH_PER + off, lane);
    load8h(a2,  g_sh + 1 * SCRATCH_PER + off, lane);
    load8h(a1,  g_sh + 2 * SCRATCH_PER + off, lane);
    load8h(a23, g_sh + 3 * SCRATCH_PER + off, lane);
    load8 (b1, lb1, lane);
    load8 (b2, lb2, lane);

    float s_cw = 0.f, s_pw1 = 0.f, s_num = 0.f, s_cc = 0.f, s_pp = 0.f;
    float pwv[8], cw1[8];
    #pragma unroll
    for (int j = 0; j < 8; j++) {
        cb[j] += b1[j];
        pb[j] += b2[j];
        pwv[j] = pb[j] * sigm(a1[j]);
        cw1[j] = cb[j] * sigm(a2[j]);
        s_cw  += cb[j] * sigm(a12[j]);
        s_pw1 += pb[j] * sigm(a23[j]);
        s_num += cb[j] * pb[j];
        s_cc  += cb[j] * cb[j];
        s_pp  += pb[j] * pb[j];
    }
    s_cw  = wsum(s_cw)  * (1.0f / 256.0f);
    s_pw1 = wsum(s_pw1) * (1.0f / 256.0f);
    s_num = wsum(s_num);
    s_cc  = wsum(s_cc);
    s_pp  = wsum(s_pp);
    const float sim = s_num / (sqrtf(s_cc) * sqrtf(s_pp));

    float co[8], po[8];
    #pragma unroll
    for (int j = 0; j < 8; j++) {
        co[j] = sigm(cb[j]) * tanh_fast(pwv[j] * s_cw);
        po[j] = sigm(pb[j]) * tanh_fast(cw1[j] * s_pw1) * sim;
    }
    store8(out + off, co, lane);
    store8(out + (size_t)B_ROWS * H_DIM + off, po, lane);
}

// ---------------- launch ----------------
extern "C" void kernel_launch(void* const* d_in, const int* in_sizes, int n_in,
                              void* d_out, int out_size) {
    const float* xc  = (const float*)d_in[0];
    const float* xp  = (const float*)d_in[1];
    const float* LW1 = (const float*)d_in[2];
    const float* LB1 = (const float*)d_in[3];
    const float* LW2 = (const float*)d_in[4];
    const float* LB2 = (const float*)d_in[5];
    const float* AW1 = (const float*)d_in[6];
    const float* AW12= (const float*)d_in[7];
    const float* AW2 = (const float*)d_in[8];
    const float* AW23= (const float*)d_in[9];
    float* out = (float*)d_out;

    wpack_kernel<<<dim3(132, 8), 256>>>(LW1, AW12, AW2, LW2, AW1, AW23);

    cudaFuncSetAttribute(gemm_f16_kernel,
                         cudaFuncAttributeMaxDynamicSharedMemorySize, SMEM_BYTES);
    gemm_f16_kernel<<<N_ROW_TILES * 12, NTHREADS, SMEM_BYTES>>>(xc, xp);

    epilogue_kernel<<<B_ROWS / 8, 256>>>(LB1, LB2, out);
}

// round 13
// speedup vs baseline: 1.4005x; 1.4005x over previous
#include <cuda_runtime.h>
#include <cuda_fp16.h>
#include <cstdint>

// ============================================================================
// InteractAttention on sm_103 (base target):
//   wpack: weights fp32 [K][256] -> fp16 n-major [256][K] via smem transpose
//   GEMM (R8 shape): 512 threads, M=128 x N=256, KCH=64, STAGES=3,
//         144B-padded smem rows (ldmatrix conflict-free), fragments via
//         ldmatrix.m8n8.x4, mma.m16n8k16.f16 fp32-accum.
//   epilogue: separate fused-row kernel.
//   g=0: xc@LW1  g=1: xc@AW12  g=2: xc@AW2  g=3: xp@LW2  g=4: xp@AW1  g=5: xp@AW23
// ============================================================================

#define B_ROWS   32768
#define H_DIM    256
#define MT       128
#define KCH      64                     // K chunk (64 halves = 128B data/row)
#define STAGES   3
#define NTHREADS 512
#define N_ROW_TILES (B_ROWS / MT)       // 256
#define SCRATCH_PER 8388608ull

__device__ __align__(16) float  g_sf[2ull * SCRATCH_PER];  // 0: cb (g0), 1: pb (g3)
__device__ __align__(16) __half g_sh[4ull * SCRATCH_PER];  // 0:a12 1:a2 2:a1 3:a23
__device__ __align__(16) __half g_wph[2162688];            // n-major fp16 weights

// half offsets of each weight matrix [256][K]
#define WH0 0u          // LW1  K=768
#define WH1 196608u     // AW12
#define WH2 393216u     // AW2
#define WH3 589824u     // LW2  K=2048
#define WH4 1114112u    // AW1
#define WH5 1638400u    // AW23

// smem rows: 128B data + 16B pad = 144B stride (36 words)
#define ROW_B        144
#define A_STAGE_B    (128 * ROW_B)            // 18432
#define B_STAGE_B    (256 * ROW_B)            // 36864
#define STAGE_BYTES  (A_STAGE_B + B_STAGE_B)  // 55296
#define SMEM_BYTES   (STAGES * STAGE_BYTES)   // 165888

__device__ __forceinline__ uint32_t smem_u32(const void* p) {
    uint32_t a;
    asm("{ .reg .u64 t; cvta.to.shared.u64 t, %1; cvt.u32.u64 %0, t; }"
        : "=r"(a) : "l"(p));
    return a;
}
__device__ __forceinline__ void cp16(uint32_t dst, const void* src) {
    asm volatile("cp.async.cg.shared.global [%0], [%1], 16;" :: "r"(dst), "l"(src));
}
__device__ __forceinline__ void ldsm_x4(uint32_t& r0, uint32_t& r1,
                                        uint32_t& r2, uint32_t& r3, uint32_t addr) {
    asm volatile("ldmatrix.sync.aligned.m8n8.x4.shared.b16 {%0,%1,%2,%3}, [%4];"
        : "=r"(r0), "=r"(r1), "=r"(r2), "=r"(r3) : "r"(addr));
}
__device__ __forceinline__ void mma_f16(float* c, const uint32_t* a, const uint32_t* b) {
    asm volatile(
        "mma.sync.aligned.m16n8k16.row.col.f32.f16.f16.f32 "
        "{%0,%1,%2,%3}, {%4,%5,%6,%7}, {%8,%9}, {%0,%1,%2,%3};"
        : "+f"(c[0]), "+f"(c[1]), "+f"(c[2]), "+f"(c[3])
        : "r"(a[0]), "r"(a[1]), "r"(a[2]), "r"(a[3]), "r"(b[0]), "r"(b[1]));
}
__device__ __forceinline__ uint32_t pack_h2(float lo, float hi) {
    __half2 h = __floats2half2_rn(lo, hi);
    return *reinterpret_cast<uint32_t*>(&h);
}

// ---------------- weight repack: fp32 [K][256] -> fp16 [256][K] -------------
__global__ void __launch_bounds__(256)
wpack_kernel(const float* __restrict__ s0, const float* __restrict__ s1,
             const float* __restrict__ s2, const float* __restrict__ s3,
             const float* __restrict__ s4, const float* __restrict__ s5) {
    __shared__ float sm[64 * 35];
    const int kb = blockIdx.x;          // 0..131
    const int nb = blockIdx.y;          // 0..7
    const float* src; int K; unsigned base; int kk;
    if      (kb < 12)  { src = s0; K = 768;  base = WH0; kk = kb; }
    else if (kb < 24)  { src = s1; K = 768;  base = WH1; kk = kb - 12; }
    else if (kb < 36)  { src = s2; K = 768;  base = WH2; kk = kb - 24; }
    else if (kb < 68)  { src = s3; K = 2048; base = WH3; kk = kb - 36; }
    else if (kb < 100) { src = s4; K = 2048; base = WH4; kk = kb - 68; }
    else               { src = s5; K = 2048; base = WH5; kk = kb - 100; }
    const int k0 = kk * 64;
    const int t  = threadIdx.x;
    const int rw = t >> 5, cl = t & 31;

    #pragma unroll
    for (int j = 0; j < 8; j++) {
        const int kr = rw + 8 * j;
        sm[kr * 35 + cl] = src[(size_t)(k0 + kr) * 256 + nb * 32 + cl];
    }
    __syncthreads();

    const int nl = t >> 3;
    const int kg = (t & 7) * 8;
    uint4 o;
    o.x = pack_h2(sm[(kg + 0) * 35 + nl], sm[(kg + 1) * 35 + nl]);
    o.y = pack_h2(sm[(kg + 2) * 35 + nl], sm[(kg + 3) * 35 + nl]);
    o.z = pack_h2(sm[(kg + 4) * 35 + nl], sm[(kg + 5) * 35 + nl]);
    o.w = pack_h2(sm[(kg + 6) * 35 + nl], sm[(kg + 7) * 35 + nl]);
    const int n = nb * 32 + nl;
    *(uint4*)(g_wph + base + (size_t)n * K + k0 + kg) = o;
}

// ---------------- GEMM ----------------
__global__ void __launch_bounds__(NTHREADS, 1)
gemm_f16_kernel(const float* __restrict__ xc, const float* __restrict__ xp) {
    extern __shared__ float smem[];
    const int tid = threadIdx.x;
    const int wid = tid >> 5;
    const int lid = tid & 31;
    const int g8  = lid >> 2;
    const int tg  = lid & 3;
    const int wm  = wid & 3;            // rows wm*32..+31
    const int wn  = wid >> 2;           // cols wn*64..+63

    // pic (K=2048) CTAs first; 3 same-tile CTAs adjacent for L2 A-sharing
    const int bid = blockIdx.x;
    int g, tile;
    if (bid < 3 * N_ROW_TILES) { tile = bid / 3; g = 3 + bid % 3; }
    else { const int b2 = bid - 3 * N_ROW_TILES; tile = b2 / 3; g = b2 % 3; }

    const float* X; const __half* Wl; int K;
    if      (g == 0) { X = xc; Wl = g_wph + WH0; K = 768;  }
    else if (g == 1) { X = xc; Wl = g_wph + WH1; K = 768;  }
    else if (g == 2) { X = xc; Wl = g_wph + WH2; K = 768;  }
    else if (g == 3) { X = xp; Wl = g_wph + WH3; K = 2048; }
    else if (g == 4) { X = xp; Wl = g_wph + WH4; K = 2048; }
    else             { X = xp; Wl = g_wph + WH5; K = 2048; }

    const float* Xb = X + (size_t)tile * MT * K;
    const uint32_t sb = smem_u32(smem);
    const int NK = K / KCH;             // 12 or 32 chunks

    // per-thread loader coords
    const int am  = tid >> 2;           // A row 0..127
    const int acv = tid & 3;            // 16-float group within 64

    float c[2][8][4];
    #pragma unroll
    for (int mt = 0; mt < 2; mt++)
        #pragma unroll
        for (int nt = 0; nt < 8; nt++)
            #pragma unroll
            for (int r = 0; r < 4; r++) c[mt][nt][r] = 0.0f;

    // fragment ldmatrix base addresses (per-thread constants)
    //   A x4: row m + (lid&15), col s*32 + (lid>>4)*16
    //   B x4: row n0 + (lid&7) + ((lid>>4)<<3), col s*32 + ((lid>>3)&1)*16
    const uint32_t aRowOff = (uint32_t)(lid & 15) * ROW_B + ((lid >> 4) << 4);
    const uint32_t bRowOff = (uint32_t)((lid & 7) + ((lid >> 4) << 3)) * ROW_B
                           + (((lid >> 3) & 1) << 4);

    auto load_B = [&](int chunk) {
        const int st = chunk % STAGES;
        const uint32_t stB = sb + st * STAGE_BYTES + A_STAGE_B;
        const int kc = chunk * KCH;
        #pragma unroll
        for (int j = 0; j < 4; j++) {
            const int f = tid + j * NTHREADS;   // 0..2047
            const int n = f >> 3;               // 0..255
            const int v = f & 7;
            cp16(stB + n * ROW_B + v * 16, Wl + (size_t)n * K + kc + v * 8);
        }
        asm volatile("cp.async.commit_group;" ::: "memory");
    };
    auto store_A = [&](int chunk, const float4* r) {
        const int st = chunk % STAGES;
        char* dst = (char*)smem + st * STAGE_BYTES + am * ROW_B + acv * 32;
        uint4 o0, o1;
        o0.x = pack_h2(r[0].x, r[0].y); o0.y = pack_h2(r[0].z, r[0].w);
        o0.z = pack_h2(r[1].x, r[1].y); o0.w = pack_h2(r[1].z, r[1].w);
        o1.x = pack_h2(r[2].x, r[2].y); o1.y = pack_h2(r[2].z, r[2].w);
        o1.z = pack_h2(r[3].x, r[3].y); o1.w = pack_h2(r[3].z, r[3].w);
        *(uint4*)(dst)      = o0;
        *(uint4*)(dst + 16) = o1;
    };
    auto load_A = [&](int chunk, float4* r) {
        const float* src = Xb + (size_t)am * K + chunk * KCH + acv * 16;
        r[0] = *(const float4*)(src + 0);
        r[1] = *(const float4*)(src + 4);
        r[2] = *(const float4*)(src + 8);
        r[3] = *(const float4*)(src + 12);
    };

    // prologue: chunks 0..STAGES-2
    #pragma unroll
    for (int s = 0; s < STAGES - 1; s++) {
        float4 r[4];
        load_A(s, r);
        store_A(s, r);
        load_B(s);
    }

    for (int i = 0; i < NK; i++) {
        asm volatile("cp.async.wait_group %0;" :: "n"(STAGES - 2) : "memory");
        __syncthreads();

        const bool pf = (i + STAGES - 1 < NK);
        float4 rA[4];
        if (pf) { load_A(i + STAGES - 1, rA); load_B(i + STAGES - 1); }

        const int st = i % STAGES;
        const uint32_t As = sb + st * STAGE_BYTES;
        const uint32_t Bs = As + A_STAGE_B;

        #pragma unroll
        for (int s = 0; s < 4; s++) {               // four k16 steps
            const uint32_t colOff = (uint32_t)(s * 32);
            uint32_t a[2][4];
            #pragma unroll
            for (int mt = 0; mt < 2; mt++) {
                const int m = wm * 32 + mt * 16;
                ldsm_x4(a[mt][0], a[mt][1], a[mt][2], a[mt][3],
                        As + (uint32_t)m * ROW_B + aRowOff + colOff);
            }
            uint32_t b[8][2];
            #pragma unroll
            for (int p = 0; p < 4; p++) {           // n-tile pairs
                const int n0 = wn * 64 + p * 16;
                ldsm_x4(b[2*p][0], b[2*p][1], b[2*p+1][0], b[2*p+1][1],
                        Bs + (uint32_t)n0 * ROW_B + bRowOff + colOff);
            }
            #pragma unroll
            for (int mt = 0; mt < 2; mt++)
                #pragma unroll
                for (int nt = 0; nt < 8; nt++)
                    mma_f16(c[mt][nt], a[mt], b[nt]);
        }

        if (pf) store_A(i + STAGES - 1, rA);
    }

    // ---- writeback ----
    if (g == 0 || g == 3) {
        float* Yf = g_sf + (size_t)(g == 0 ? 0 : 1) * SCRATCH_PER
                         + (size_t)tile * (MT * H_DIM);
        #pragma unroll
        for (int mt = 0; mt < 2; mt++) {
            const int r0 = wm * 32 + mt * 16 + g8;
            #pragma unroll
            for (int nt = 0; nt < 8; nt++) {
                const int col = wn * 64 + nt * 8 + tg * 2;
                *(float2*)(Yf + (size_t)r0 * H_DIM + col) =
                    make_float2(c[mt][nt][0], c[mt][nt][1]);
                *(float2*)(Yf + (size_t)(r0 + 8) * H_DIM + col) =
                    make_float2(c[mt][nt][2], c[mt][nt][3]);
            }
        }
    } else {
        const int idx = (g == 1) ? 0 : (g == 2) ? 1 : (g == 4) ? 2 : 3;
        __half* Yh = g_sh + (size_t)idx * SCRATCH_PER
                          + (size_t)tile * (MT * H_DIM);
        #pragma unroll
        for (int mt = 0; mt < 2; mt++) {
            const int r0 = wm * 32 + mt * 16 + g8;
            #pragma unroll
            for (int nt = 0; nt < 8; nt++) {
                const int col = wn * 64 + nt * 8 + tg * 2;
                *(uint32_t*)(Yh + (size_t)r0 * H_DIM + col) =
                    pack_h2(c[mt][nt][0], c[mt][nt][1]);
                *(uint32_t*)(Yh + (size_t)(r0 + 8) * H_DIM + col) =
                    pack_h2(c[mt][nt][2], c[mt][nt][3]);
            }
        }
    }
}

// ---------------- epilogue: one warp per row ----------------
__device__ __forceinline__ float wsum(float v) {
    #pragma unroll
    for (int o = 16; o; o >>= 1) v += __shfl_xor_sync(0xFFFFFFFFu, v, o);
    return v;
}
__device__ __forceinline__ void load8(float* a, const float* base, int lane) {
    const float4* p = (const float4*)base;
    float4 x = p[lane], y = p[lane + 32];
    a[0]=x.x; a[1]=x.y; a[2]=x.z; a[3]=x.w;
    a[4]=y.x; a[5]=y.y; a[6]=y.z; a[7]=y.w;
}
__device__ __forceinline__ void load8h(float* a, const __half* base, int lane) {
    const uint2* p = (const uint2*)base;
    uint2 x = p[lane], y = p[lane + 32];
    float2 f;
    f = __half22float2(*(__half2*)&x.x); a[0]=f.x; a[1]=f.y;
    f = __half22float2(*(__half2*)&x.y); a[2]=f.x; a[3]=f.y;
    f = __half22float2(*(__half2*)&y.x); a[4]=f.x; a[5]=f.y;
    f = __half22float2(*(__half2*)&y.y); a[6]=f.x; a[7]=f.y;
}
__device__ __forceinline__ void store8(float* base, const float* a, int lane) {
    float4* p = (float4*)base;
    p[lane]      = make_float4(a[0], a[1], a[2], a[3]);
    p[lane + 32] = make_float4(a[4], a[5], a[6], a[7]);
}
__device__ __forceinline__ float sigm(float x) { return 1.0f / (1.0f + __expf(-x)); }
__device__ __forceinline__ float tanh_fast(float x) {
    return 1.0f - 2.0f / (1.0f + __expf(2.0f * x));
}

__global__ void __launch_bounds__(256)
epilogue_kernel(const float* __restrict__ lb1, const float* __restrict__ lb2,
                float* __restrict__ out) {
    const int lane = threadIdx.x & 31;
    const int row  = blockIdx.x * 8 + (threadIdx.x >> 5);
    const size_t off = (size_t)row * H_DIM;

    float cb[8], a12[8], a2[8], pb[8], a1[8], a23[8], b1[8], b2[8];
    load8 (cb,  g_sf + 0 * SCRATCH_PER + off, lane);
    load8 (pb,  g_sf + 1 * SCRATCH_PER + off, lane);
    load8h(a12, g_sh + 0 * SCRATCH_PER + off, lane);
    load8h(a2,  g_sh + 1 * SCRATCH_PER + off, lane);
    load8h(a1,  g_sh + 2 * SCRATCH_PER + off, lane);
    load8h(a23, g_sh + 3 * SCRATCH_PER + off, lane);
    load8 (b1, lb1, lane);
    load8 (b2, lb2, lane);

    float s_cw = 0.f, s_pw1 = 0.f, s_num = 0.f, s_cc = 0.f, s_pp = 0.f;
    float pwv[8], cw1[8];
    #pragma unroll
    for (int j = 0; j < 8; j++) {
        cb[j] += b1[j];
        pb[j] += b2[j];
        pwv[j] = pb[j] * sigm(a1[j]);
        cw1[j] = cb[j] * sigm(a2[j]);
        s_cw  += cb[j] * sigm(a12[j]);
        s_pw1 += pb[j] * sigm(a23[j]);
        s_num += cb[j] * pb[j];
        s_cc  += cb[j] * cb[j];
        s_pp  += pb[j] * pb[j];
    }
    s_cw  = wsum(s_cw)  * (1.0f / 256.0f);
    s_pw1 = wsum(s_pw1) * (1.0f / 256.0f);
    s_num = wsum(s_num);
    s_cc  = wsum(s_cc);
    s_pp  = wsum(s_pp);
    const float sim = s_num / (sqrtf(s_cc) * sqrtf(s_pp));

    float co[8], po[8];
    #pragma unroll
    for (int j = 0; j < 8; j++) {
        co[j] = sigm(cb[j]) * tanh_fast(pwv[j] * s_cw);
        po[j] = sigm(pb[j]) * tanh_fast(cw1[j] * s_pw1) * sim;
    }
    store8(out + off, co, lane);
    store8(out + (size_t)B_ROWS * H_DIM + off, po, lane);
}

// ---------------- launch ----------------
extern "C" void kernel_launch(void* const* d_in, const int* in_sizes, int n_in,
                              void* d_out, int out_size) {
    const float* xc  = (const float*)d_in[0];
    const float* xp  = (const float*)d_in[1];
    const float* LW1 = (const float*)d_in[2];
    const float* LB1 = (const float*)d_in[3];
    const float* LW2 = (const float*)d_in[4];
    const float* LB2 = (const float*)d_in[5];
    const float* AW1 = (const float*)d_in[6];
    const float* AW12= (const float*)d_in[7];
    const float* AW2 = (const float*)d_in[8];
    const float* AW23= (const float*)d_in[9];
    float* out = (float*)d_out;

    wpack_kernel<<<dim3(132, 8), 256>>>(LW1, AW12, AW2, LW2, AW1, AW23);

    cudaFuncSetAttribute(gemm_f16_kernel,
                         cudaFuncAttributeMaxDynamicSharedMemorySize, SMEM_BYTES);
    gemm_f16_kernel<<<N_ROW_TILES * 6, NTHREADS, SMEM_BYTES>>>(xc, xp);

    epilogue_kernel<<<B_ROWS / 8, 256>>>(LB1, LB2, out);
}